// round 4
// baseline (speedup 1.0000x reference)
#include <cuda_runtime.h>
#include <cuda_bf16.h>
#include <cstdint>
#include <math.h>

#define NROWS 16384
#define NHALF 8192
#define DDIM  256
#define NT    128
#define NTRI  8256            // NT*(NT+1)/2 upper-tri tiles
#define CHUNK 4
#define NCHUNK ((NTRI + CHUNK - 1) / CHUNK)   // 2064
#define GT    256
#define GRID_P 152

// ---- device scratch ----
__device__ __nv_bfloat16 g_zn[NROWS * DDIM];
__device__ float  g_pos[NROWS];
__device__ float  g_S[NROWS];
__device__ double g_part[64];
__device__ int    g_ticket;
__device__ int    g_done = 0;

// ---- gemm smem ----
#define OFF_A    0
#define OFF_B0   65536
#define OFF_B1   131072
#define OFF_BC   196608
#define SMEM_TOTAL 196624

// ============================ helpers ============================
__device__ __forceinline__ uint32_t smem_u32(const void* p) {
    uint32_t a;
    asm("{ .reg .u64 t; cvta.to.shared.u64 t, %1; cvt.u32.u64 %0, t; }"
        : "=r"(a) : "l"(p));
    return a;
}
__device__ __forceinline__ void ldsm_x4(uint32_t& r0, uint32_t& r1,
                                        uint32_t& r2, uint32_t& r3,
                                        uint32_t addr) {
    asm volatile("ldmatrix.sync.aligned.m8n8.x4.shared.b16 {%0,%1,%2,%3}, [%4];"
                 : "=r"(r0), "=r"(r1), "=r"(r2), "=r"(r3) : "r"(addr));
}
__device__ __forceinline__ void mma16816(float* d, const uint32_t* a,
                                         uint32_t b0, uint32_t b1) {
    asm volatile(
        "mma.sync.aligned.m16n8k16.row.col.f32.bf16.bf16.f32 "
        "{%0,%1,%2,%3}, {%4,%5,%6,%7}, {%8,%9}, {%0,%1,%2,%3};"
        : "+f"(d[0]), "+f"(d[1]), "+f"(d[2]), "+f"(d[3])
        : "r"(a[0]), "r"(a[1]), "r"(a[2]), "r"(a[3]), "r"(b0), "r"(b1));
}
__device__ __forceinline__ float ex2f(float x) {
    float y; asm("ex2.approx.f32 %0, %1;" : "=f"(y) : "f"(x)); return y;
}
__device__ __forceinline__ void cp_commit() {
    asm volatile("cp.async.commit_group;" ::: "memory");
}
__device__ __forceinline__ void cp_wait0() {
    asm volatile("cp.async.wait_group 0;" ::: "memory");
}
__device__ __forceinline__ void cp_tile(uint32_t sdst, int rowblk, int tid) {
    const char* gp = reinterpret_cast<const char*>(g_zn) + (size_t)rowblk * 65536;
    #pragma unroll
    for (int it = 0; it < 16; ++it) {
        int c = tid + it * GT;
        int r = c >> 5, cc = c & 31;
        uint32_t d = sdst + r * 512 + (((cc ^ (r & 7))) << 4);
        asm volatile("cp.async.cg.shared.global [%0], [%1], 16;"
                     :: "r"(d), "l"(gp + (size_t)c * 16) : "memory");
    }
}
__device__ __forceinline__ void decode_tile(int T, int& bi, int& bj) {
    int b = (int)((257.0f - sqrtf((float)(66049 - 8 * T))) * 0.5f);
    b = max(0, min(127, b));
    while (b * (257 - b) / 2 > T) --b;
    while ((b + 1) * (256 - b) / 2 <= T) ++b;
    bi = b;
    bj = b + (T - b * (257 - b) / 2);
}

#define C1F 14.42695040888963f   // 10*log2(e)

// ============================ epilogue slice ============================
template <bool MASK>
__device__ __forceinline__ void epi_slice(int kk, float (&accE)[2][8][4],
    float (&rsum)[2][2], float (&csum)[8][2], float bias,
    uint32_t d0, uint32_t d1, uint32_t d2, uint32_t d3) {
    const int mf = kk >> 3, nf = kk & 7;
    #pragma unroll
    for (int e = 0; e < 4; ++e) {
        float ev = ex2f(fmaf(accE[mf][nf][e], C1F, bias));
        if (MASK) {
            uint32_t id = (uint32_t)(kk * 4 + e);
            if (id == d0 || id == d1 || id == d2 || id == d3) ev = 0.f;
        }
        rsum[mf][e >> 1] += ev;
        csum[nf][e & 1] += ev;
        accE[mf][nf][e] = 0.f;
    }
}

template <bool MASK>
__device__ __forceinline__ void epi_only(float (&accE)[2][8][4],
    float (&rsum)[2][2], float (&csum)[8][2], float bias,
    uint32_t d0, uint32_t d1, uint32_t d2, uint32_t d3) {
    #pragma unroll
    for (int kk = 0; kk < 16; ++kk)
        epi_slice<MASK>(kk, accE, rsum, csum, bias, d0, d1, d2, d3);
}

// ===================== fused k-loop: MMA(accW) + epilogue(accE) =====================
template <bool MASK>
__device__ __forceinline__ void kloop(
    float (&accW)[2][8][4], float (&accE)[2][8][4],
    float (&rsum)[2][2], float (&csum)[8][2],
    const uint32_t (&aB)[2], int aR7, int aSel,
    const uint32_t (&bB)[4], int bR7, int bSel, uint32_t bofs,
    float bias, uint32_t d0, uint32_t d1, uint32_t d2, uint32_t d3) {
    #pragma unroll
    for (int kk = 0; kk < 16; ++kk) {
        uint32_t a[2][4], b[4][4];
        uint32_t aoff = (uint32_t)(((2 * kk + aSel) ^ aR7) << 4);
        ldsm_x4(a[0][0], a[0][1], a[0][2], a[0][3], aB[0] + aoff);
        ldsm_x4(a[1][0], a[1][1], a[1][2], a[1][3], aB[1] + aoff);
        uint32_t boff = (uint32_t)(((2 * kk + bSel) ^ bR7) << 4) + bofs;
        #pragma unroll
        for (int p = 0; p < 4; ++p)
            ldsm_x4(b[p][0], b[p][1], b[p][2], b[p][3], bB[p] + boff);
        #pragma unroll
        for (int mf = 0; mf < 2; ++mf)
            #pragma unroll
            for (int nf = 0; nf < 8; ++nf)
                mma16816(accW[mf][nf], a[mf],
                         b[nf >> 1][(nf & 1) * 2], b[nf >> 1][(nf & 1) * 2 + 1]);
        epi_slice<MASK>(kk, accE, rsum, csum, bias, d0, d1, d2, d3);
    }
}

// ============================ K1: normalize + positives ============================
__global__ void norm_pos_kernel(const float* __restrict__ z1,
                                const float* __restrict__ z2) {
    int r = blockIdx.x;           // 0..8191
    int t = threadIdx.x;          // 0..127
    int half = t >> 6, tt = t & 63;
    const float* src = (half ? z2 : z1) + (size_t)r * DDIM;
    float4 v = reinterpret_cast<const float4*>(src)[tt];
    float ss = v.x * v.x + v.y * v.y + v.z * v.z + v.w * v.w;
    #pragma unroll
    for (int o = 16; o; o >>= 1) ss += __shfl_xor_sync(0xffffffffu, ss, o);
    __shared__ float ws[4];
    __shared__ float sn[2][256];
    if ((t & 31) == 0) ws[t >> 5] = ss;
    __syncthreads();
    float inv = 1.0f / fmaxf(sqrtf(ws[half * 2] + ws[half * 2 + 1]), 1e-6f);
    float4 n;
    n.x = v.x * inv; n.y = v.y * inv; n.z = v.z * inv; n.w = v.w * inv;
    __nv_bfloat162 h0 = __floats2bfloat162_rn(n.x, n.y);
    __nv_bfloat162 h1 = __floats2bfloat162_rn(n.z, n.w);
    uint2 packed;
    packed.x = *reinterpret_cast<uint32_t*>(&h0);
    packed.y = *reinterpret_cast<uint32_t*>(&h1);
    int row = half ? r + NHALF : r;
    reinterpret_cast<uint2*>(g_zn + (size_t)row * DDIM)[tt] = packed;
    reinterpret_cast<float4*>(sn[half])[tt] = n;
    __syncthreads();
    // fp32 positive dot: 128 threads x 2 elements
    float p = sn[0][t * 2] * sn[1][t * 2] + sn[0][t * 2 + 1] * sn[1][t * 2 + 1];
    #pragma unroll
    for (int o = 16; o; o >>= 1) p += __shfl_xor_sync(0xffffffffu, p, o);
    if ((t & 31) == 0) ws[t >> 5] = p;
    __syncthreads();
    if (t == 0) {
        float d = fminf(fmaxf(ws[0] + ws[1] + ws[2] + ws[3], -1.0f + 1e-6f),
                        1.0f - 1e-6f);
        g_pos[r] = d;
        g_pos[r + NHALF] = d;
        g_S[r] = 0.f;
        g_S[r + NHALF] = 0.f;
        if (r == 0) g_ticket = 0;
    }
}

// ===================== K2: persistent symmetric GEMM + LSE =====================
__global__ void __launch_bounds__(GT, 1) gemm_sym_kernel() {
    extern __shared__ char smem[];
    const int tid = threadIdx.x, lane = tid & 31, wid = tid >> 5;
    const int wm = wid & 3, wn = wid >> 2;
    const int g = lane >> 2, q = lane & 3;
    uint32_t sb = smem_u32(smem);
    int* sBC = reinterpret_cast<int*>(smem + OFF_BC);

    // fragment addressing (proven R1/R3 scheme)
    const int aRow = lane & 15;
    const int aSel = lane >> 4;
    const int bRowOff = (lane & 7) + ((lane >> 4) << 3);
    const int bSel = (lane >> 3) & 1;
    const int aR7 = aRow & 7, bR7 = bRowOff & 7;
    uint32_t aB[2], bB[4];
    #pragma unroll
    for (int mf = 0; mf < 2; ++mf)
        aB[mf] = sb + OFF_A + (wm * 32 + mf * 16 + aRow) * 512;
    #pragma unroll
    for (int p = 0; p < 4; ++p)
        bB[p] = sb + OFF_B0 + (wn * 64 + p * 16 + bRowOff) * 512;

    // per-thread diag element ids (4, or 255 sentinel)
    const bool qual = ((wm >> 1) == wn) && (q == (g >> 1));
    const int bbit = g & 1;
    uint32_t dd[4];
    #pragma unroll
    for (int mf = 0; mf < 2; ++mf)
        #pragma unroll
        for (int h = 0; h < 2; ++h) {
            int nf = (wm & 1) * 4 + mf * 2 + h;
            dd[mf * 2 + h] = qual ? (uint32_t)((mf * 8 + nf) * 4 + h * 2 + bbit)
                                  : 255u;
        }

    float accA[2][8][4], accB[2][8][4];
    float rsum[2][2] = {{0.f, 0.f}, {0.f, 0.f}};
    float csum[8][2];
    #pragma unroll
    for (int mf = 0; mf < 2; ++mf)
        #pragma unroll
        for (int nf = 0; nf < 8; ++nf)
            #pragma unroll
            for (int e = 0; e < 4; ++e) { accA[mf][nf][e] = 0.f; accB[mf][nf][e] = 0.f; }
    #pragma unroll
    for (int nf = 0; nf < 8; ++nf) { csum[nf][0] = 0.f; csum[nf][1] = 0.f; }

    const float NEGINF = __int_as_float(0xff800000);
    int cur_bi = -1, pbj = 0, par = 0;
    bool hp = false, pdiag = false;

    for (;;) {
        if (tid == 0) sBC[0] = atomicAdd(&g_ticket, 1);
        __syncthreads();
        int c = sBC[0];
        if (c >= NCHUNK) break;
        int T0 = c * CHUNK, T1 = min(T0 + CHUNK, NTRI);

        for (int T = T0; T < T1; ++T) {
            int bi, bj;
            decode_tile(T, bi, bj);
            if (T == T0 || bi != cur_bi) {
                // ---- boundary: issue loads, drain pending in their shadow ----
                __syncthreads();
                if (bi != cur_bi) cp_tile(sb + OFF_A, bi, tid);
                cp_tile(sb + OFF_B0, bj, tid);
                cp_commit();
                if (hp) {
                    if (pdiag) epi_only<true >(par ? accA : accB, rsum, csum,
                                               -C1F, dd[0], dd[1], dd[2], dd[3]);
                    else       epi_only<false>(par ? accA : accB, rsum, csum,
                                               -C1F, dd[0], dd[1], dd[2], dd[3]);
                    if (!pdiag) {
                        #pragma unroll
                        for (int nf = 0; nf < 8; ++nf)
                            #pragma unroll
                            for (int e1 = 0; e1 < 2; ++e1) {
                                float v = csum[nf][e1];
                                v += __shfl_xor_sync(0xffffffffu, v, 4);
                                v += __shfl_xor_sync(0xffffffffu, v, 8);
                                v += __shfl_xor_sync(0xffffffffu, v, 16);
                                if (g == 0)
                                    atomicAdd(&g_S[pbj * 128 + wn * 64 + nf * 8 + q * 2 + e1], v);
                            }
                    }
                    #pragma unroll
                    for (int nf = 0; nf < 8; ++nf) { csum[nf][0] = 0.f; csum[nf][1] = 0.f; }
                    hp = false;
                }
                if (cur_bi >= 0 && bi != cur_bi) {
                    #pragma unroll
                    for (int mf = 0; mf < 2; ++mf)
                        #pragma unroll
                        for (int h = 0; h < 2; ++h) {
                            float v = rsum[mf][h];
                            v += __shfl_xor_sync(0xffffffffu, v, 1);
                            v += __shfl_xor_sync(0xffffffffu, v, 2);
                            if (q == 0)
                                atomicAdd(&g_S[cur_bi * 128 + wm * 32 + mf * 16 + h * 8 + g], v);
                            rsum[mf][h] = 0.f;
                        }
                }
                cur_bi = bi;
                par = 0;
            }

            cp_wait0();
            __syncthreads();
            // prefetch next tile's B (same row, same chunk)
            if (T + 1 < T1 && bj + 1 < NT) {
                cp_tile(sb + (par ? OFF_B0 : OFF_B1), bj + 1, tid);
                cp_commit();
            }
            float bias = hp ? -C1F : NEGINF;
            uint32_t bofs = (uint32_t)par * 65536u;
            bool maskP = hp && pdiag;
            if (maskP) {
                if (par) kloop<true >(accB, accA, rsum, csum, aB, aR7, aSel,
                                      bB, bR7, bSel, bofs, bias, dd[0], dd[1], dd[2], dd[3]);
                else     kloop<true >(accA, accB, rsum, csum, aB, aR7, aSel,
                                      bB, bR7, bSel, bofs, bias, dd[0], dd[1], dd[2], dd[3]);
            } else {
                if (par) kloop<false>(accB, accA, rsum, csum, aB, aR7, aSel,
                                      bB, bR7, bSel, bofs, bias, dd[0], dd[1], dd[2], dd[3]);
                else     kloop<false>(accA, accB, rsum, csum, aB, aR7, aSel,
                                      bB, bR7, bSel, bofs, bias, dd[0], dd[1], dd[2], dd[3]);
            }
            // finalize prev tile's column sums (tensor pipe still draining)
            if (hp && !pdiag) {
                #pragma unroll
                for (int nf = 0; nf < 8; ++nf)
                    #pragma unroll
                    for (int e1 = 0; e1 < 2; ++e1) {
                        float v = csum[nf][e1];
                        v += __shfl_xor_sync(0xffffffffu, v, 4);
                        v += __shfl_xor_sync(0xffffffffu, v, 8);
                        v += __shfl_xor_sync(0xffffffffu, v, 16);
                        if (g == 0)
                            atomicAdd(&g_S[pbj * 128 + wn * 64 + nf * 8 + q * 2 + e1], v);
                    }
            }
            if (hp) {
                #pragma unroll
                for (int nf = 0; nf < 8; ++nf) { csum[nf][0] = 0.f; csum[nf][1] = 0.f; }
            }
            hp = true;
            pdiag = (bi == bj);
            pbj = bj;
            par ^= 1;
        }
    }

    // ---- final drain ----
    if (hp) {
        if (pdiag) epi_only<true >(par ? accA : accB, rsum, csum, -C1F,
                                   dd[0], dd[1], dd[2], dd[3]);
        else       epi_only<false>(par ? accA : accB, rsum, csum, -C1F,
                                   dd[0], dd[1], dd[2], dd[3]);
        if (!pdiag) {
            #pragma unroll
            for (int nf = 0; nf < 8; ++nf)
                #pragma unroll
                for (int e1 = 0; e1 < 2; ++e1) {
                    float v = csum[nf][e1];
                    v += __shfl_xor_sync(0xffffffffu, v, 4);
                    v += __shfl_xor_sync(0xffffffffu, v, 8);
                    v += __shfl_xor_sync(0xffffffffu, v, 16);
                    if (g == 0)
                        atomicAdd(&g_S[pbj * 128 + wn * 64 + nf * 8 + q * 2 + e1], v);
                }
        }
    }
    if (cur_bi >= 0) {
        #pragma unroll
        for (int mf = 0; mf < 2; ++mf)
            #pragma unroll
            for (int h = 0; h < 2; ++h) {
                float v = rsum[mf][h];
                v += __shfl_xor_sync(0xffffffffu, v, 1);
                v += __shfl_xor_sync(0xffffffffu, v, 2);
                if (q == 0)
                    atomicAdd(&g_S[cur_bi * 128 + wm * 32 + mf * 16 + h * 8 + g], v);
            }
    }
}

// ============================ K3: loss (single kernel) ============================
__global__ void loss_kernel(float* __restrict__ out) {
    int r = blockIdx.x * 256 + threadIdx.x;
    double v = (double)logf(g_S[r]) + 10.0 - 10.0 * (double)g_pos[r];
    #pragma unroll
    for (int o = 16; o; o >>= 1) v += __shfl_xor_sync(0xffffffffu, v, o);
    __shared__ double sd[8];
    if ((threadIdx.x & 31) == 0) sd[threadIdx.x >> 5] = v;
    __syncthreads();
    if (threadIdx.x == 0) {
        double a = 0.0;
        #pragma unroll
        for (int i = 0; i < 8; ++i) a += sd[i];
        g_part[blockIdx.x] = a;
        __threadfence();
        int n = atomicAdd(&g_done, 1);
        if (n == 63) {
            __threadfence();
            double s = 0.0;
            for (int i = 0; i < 64; ++i)
                s += *((volatile double*)&g_part[i]);
            out[0] = (float)(s / (double)NROWS);
            g_done = 0;
        }
    }
}

// ---------------------------------------------------------------------------
extern "C" void kernel_launch(void* const* d_in, const int* in_sizes, int n_in,
                              void* d_out, int out_size) {
    (void)in_sizes; (void)n_in; (void)out_size;
    const float* z1 = (const float*)d_in[0];
    const float* z2 = (const float*)d_in[1];
    float* out = (float*)d_out;

    cudaFuncSetAttribute(gemm_sym_kernel,
                         cudaFuncAttributeMaxDynamicSharedMemorySize, SMEM_TOTAL);

    norm_pos_kernel<<<NHALF, 128>>>(z1, z2);
    gemm_sym_kernel<<<GRID_P, GT, SMEM_TOTAL>>>();
    loss_kernel<<<64, 256>>>(out);
}

// round 5
// speedup vs baseline: 1.3193x; 1.3193x over previous
#include <cuda_runtime.h>
#include <cuda_bf16.h>
#include <cstdint>
#include <math.h>

#define NROWS 16384
#define NHALF 8192
#define DDIM  256
#define NT    128
#define SEGW  8
#define NSEG  1088          // sum_bi ceil((128-bi)/8)
#define GT    256
#define GRID_P 152

// ---- device scratch ----
__device__ __nv_bfloat16 g_zn[NROWS * DDIM];
__device__ float  g_pos[NROWS];
__device__ float  g_S[NROWS];
__device__ double g_part[64];
__device__ int    g_ticket;
__device__ int    g_done = 0;

// ---- gemm smem ----
#define OFF_A    0
#define OFF_B0   65536
#define OFF_B1   131072
#define OFF_BC   196608
#define SMEM_TOTAL 196624

#define C1F 14.42695040888963f   // 10*log2(e)

// ============================ helpers ============================
__device__ __forceinline__ uint32_t smem_u32(const void* p) {
    uint32_t a;
    asm("{ .reg .u64 t; cvta.to.shared.u64 t, %1; cvt.u32.u64 %0, t; }"
        : "=r"(a) : "l"(p));
    return a;
}
__device__ __forceinline__ void ldsm_x4(uint32_t& r0, uint32_t& r1,
                                        uint32_t& r2, uint32_t& r3,
                                        uint32_t addr) {
    asm volatile("ldmatrix.sync.aligned.m8n8.x4.shared.b16 {%0,%1,%2,%3}, [%4];"
                 : "=r"(r0), "=r"(r1), "=r"(r2), "=r"(r3) : "r"(addr));
}
__device__ __forceinline__ void mma16816(float* d, const uint32_t* a,
                                         uint32_t b0, uint32_t b1) {
    asm volatile(
        "mma.sync.aligned.m16n8k16.row.col.f32.bf16.bf16.f32 "
        "{%0,%1,%2,%3}, {%4,%5,%6,%7}, {%8,%9}, {%0,%1,%2,%3};"
        : "+f"(d[0]), "+f"(d[1]), "+f"(d[2]), "+f"(d[3])
        : "r"(a[0]), "r"(a[1]), "r"(a[2]), "r"(a[3]), "r"(b0), "r"(b1));
}
__device__ __forceinline__ float ex2f(float x) {
    float y; asm("ex2.approx.f32 %0, %1;" : "=f"(y) : "f"(x)); return y;
}
__device__ __forceinline__ void cp_commit() {
    asm volatile("cp.async.commit_group;" ::: "memory");
}
__device__ __forceinline__ void cp_wait0() {
    asm volatile("cp.async.wait_group 0;" ::: "memory");
}
__device__ __forceinline__ void cp_tile(uint32_t sdst, int rowblk, int tid) {
    const char* gp = reinterpret_cast<const char*>(g_zn) + (size_t)rowblk * 65536;
    #pragma unroll
    for (int it = 0; it < 16; ++it) {
        int c = tid + it * GT;
        int r = c >> 5, cc = c & 31;
        uint32_t d = sdst + r * 512 + (((cc ^ (r & 7))) << 4);
        asm volatile("cp.async.cg.shared.global [%0], [%1], 16;"
                     :: "r"(d), "l"(gp + (size_t)c * 16) : "memory");
    }
}

// ============================ K1: normalize + positives ============================
__global__ void norm_pos_kernel(const float* __restrict__ z1,
                                const float* __restrict__ z2) {
    int r = blockIdx.x;           // 0..8191
    int t = threadIdx.x;          // 0..127
    int half = t >> 6, tt = t & 63;
    const float* src = (half ? z2 : z1) + (size_t)r * DDIM;
    float4 v = reinterpret_cast<const float4*>(src)[tt];
    float ss = v.x * v.x + v.y * v.y + v.z * v.z + v.w * v.w;
    #pragma unroll
    for (int o = 16; o; o >>= 1) ss += __shfl_xor_sync(0xffffffffu, ss, o);
    __shared__ float ws[4];
    __shared__ float sn[2][256];
    if ((t & 31) == 0) ws[t >> 5] = ss;
    __syncthreads();
    float inv = 1.0f / fmaxf(sqrtf(ws[half * 2] + ws[half * 2 + 1]), 1e-6f);
    float4 n;
    n.x = v.x * inv; n.y = v.y * inv; n.z = v.z * inv; n.w = v.w * inv;
    __nv_bfloat162 h0 = __floats2bfloat162_rn(n.x, n.y);
    __nv_bfloat162 h1 = __floats2bfloat162_rn(n.z, n.w);
    uint2 packed;
    packed.x = *reinterpret_cast<uint32_t*>(&h0);
    packed.y = *reinterpret_cast<uint32_t*>(&h1);
    int row = half ? r + NHALF : r;
    reinterpret_cast<uint2*>(g_zn + (size_t)row * DDIM)[tt] = packed;
    reinterpret_cast<float4*>(sn[half])[tt] = n;
    __syncthreads();
    float p = sn[0][t * 2] * sn[1][t * 2] + sn[0][t * 2 + 1] * sn[1][t * 2 + 1];
    #pragma unroll
    for (int o = 16; o; o >>= 1) p += __shfl_xor_sync(0xffffffffu, p, o);
    if ((t & 31) == 0) ws[t >> 5] = p;
    __syncthreads();
    if (t == 0) {
        float d = fminf(fmaxf(ws[0] + ws[1] + ws[2] + ws[3], -1.0f + 1e-6f),
                        1.0f - 1e-6f);
        g_pos[r] = d;
        g_pos[r + NHALF] = d;
        g_S[r] = 0.f;
        g_S[r + NHALF] = 0.f;
        if (r == 0) g_ticket = 0;
    }
}

// ===================== K2: persistent symmetric GEMM + LSE =====================
template <bool MASK>
__device__ __forceinline__ void epilogue(float (&acc)[2][8][4],
                                         float (&rsum)[2][2],
                                         int colbase,   // bj*128 + wn*64
                                         int lane, const uint32_t* dd) {
    const int g = lane >> 2, q = lane & 3;
    float csum[8][2];
    #pragma unroll
    for (int nf = 0; nf < 8; ++nf) { csum[nf][0] = 0.f; csum[nf][1] = 0.f; }
    #pragma unroll
    for (int mf = 0; mf < 2; ++mf)
        #pragma unroll
        for (int nf = 0; nf < 8; ++nf)
            #pragma unroll
            for (int e = 0; e < 4; ++e) {
                float ev = ex2f(fmaf(acc[mf][nf][e], C1F, -C1F));
                if (MASK) {
                    uint32_t id = (uint32_t)(((mf * 8 + nf) << 2) + e);
                    if (id == dd[0] || id == dd[1] || id == dd[2] || id == dd[3])
                        ev = 0.f;
                }
                rsum[mf][e >> 1] += ev;
                if (!MASK) csum[nf][e & 1] += ev;
                acc[mf][nf][e] = 0.f;
            }
    if (!MASK) {
        #pragma unroll
        for (int nf = 0; nf < 8; ++nf)
            #pragma unroll
            for (int e1 = 0; e1 < 2; ++e1) {
                float v = csum[nf][e1];
                v += __shfl_xor_sync(0xffffffffu, v, 4);
                v += __shfl_xor_sync(0xffffffffu, v, 8);
                v += __shfl_xor_sync(0xffffffffu, v, 16);
                if (g == 0)
                    atomicAdd(&g_S[colbase + nf * 8 + q * 2 + e1], v);
            }
    }
}

__device__ __forceinline__ void flush_rsum(float (&rsum)[2][2], int bi,
                                           int wm, int lane) {
    const int g = lane >> 2, q = lane & 3;
    #pragma unroll
    for (int mf = 0; mf < 2; ++mf)
        #pragma unroll
        for (int h = 0; h < 2; ++h) {
            float v = rsum[mf][h];
            v += __shfl_xor_sync(0xffffffffu, v, 1);
            v += __shfl_xor_sync(0xffffffffu, v, 2);
            if (q == 0)
                atomicAdd(&g_S[bi * 128 + wm * 32 + mf * 16 + h * 8 + g], v);
            rsum[mf][h] = 0.f;
        }
}

__global__ void __launch_bounds__(GT, 1) gemm_sym_kernel() {
    extern __shared__ char smem[];
    const int tid = threadIdx.x, lane = tid & 31, wid = tid >> 5;
    const int wm = wid & 3, wn = wid >> 2;
    const int g = lane >> 2, q = lane & 3;
    uint32_t sb = smem_u32(smem);
    int* sBC = reinterpret_cast<int*>(smem + OFF_BC);

    // fragment addressing (proven scheme)
    const int aRow = lane & 15;
    const int aSel = lane >> 4;
    const int bRowOff = (lane & 7) + ((lane >> 4) << 3);
    const int bSel = (lane >> 3) & 1;
    const int aR7 = aRow & 7, bR7 = bRowOff & 7;
    uint32_t aB[2], bB[4];
    #pragma unroll
    for (int mf = 0; mf < 2; ++mf)
        aB[mf] = sb + OFF_A + (wm * 32 + mf * 16 + aRow) * 512;
    #pragma unroll
    for (int p = 0; p < 4; ++p)
        bB[p] = sb + OFF_B0 + (wn * 64 + p * 16 + bRowOff) * 512;

    // per-thread diag element ids (4 or 255 sentinel); verified R4 (rel_err 0)
    const bool qual = ((wm >> 1) == wn) && (q == (g >> 1));
    const int bbit = g & 1;
    uint32_t dd[4];
    #pragma unroll
    for (int mf = 0; mf < 2; ++mf)
        #pragma unroll
        for (int h = 0; h < 2; ++h) {
            int nf = (wm & 1) * 4 + mf * 2 + h;
            dd[mf * 2 + h] = qual ? (uint32_t)(((mf * 8 + nf) << 2) + h * 2 + bbit)
                                  : 255u;
        }

    float acc[2][8][4];
    #pragma unroll
    for (int mf = 0; mf < 2; ++mf)
        #pragma unroll
        for (int nf = 0; nf < 8; ++nf)
            #pragma unroll
            for (int e = 0; e < 4; ++e) acc[mf][nf][e] = 0.f;
    float rsum[2][2] = {{0.f, 0.f}, {0.f, 0.f}};

    int cur_bi = -1;

    for (;;) {
        if (tid == 0) sBC[0] = atomicAdd(&g_ticket, 1);
        __syncthreads();            // broadcast + all warps past prior kloop
        int c = sBC[0];
        if (c >= NSEG) break;

        // decode segment -> (bi, j0, len)
        int idx = c, bi = 0;
        for (;;) {
            int ns = (NT - bi + SEGW - 1) >> 3;
            if (idx < ns) break;
            idx -= ns; ++bi;
        }
        const int j0 = bi + idx * SEGW;
        const int len = min(SEGW, NT - j0);

        if (bi != cur_bi) {
            if (cur_bi >= 0) flush_rsum(rsum, cur_bi, wm, lane);
            cp_tile(sb + OFF_A, bi, tid);
            cur_bi = bi;
        }
        cp_tile(sb + OFF_B0, j0, tid);
        cp_commit();

        for (int t = 0; t < len; ++t) {
            const int par = t & 1;
            cp_wait0();
            __syncthreads();        // B[t] (+A) visible to all warps
            if (t + 1 < len) {
                cp_tile(sb + (par ? OFF_B0 : OFF_B1), j0 + t + 1, tid);
                cp_commit();
            }
            const uint32_t bofs = (uint32_t)par * 65536u;

            // ---- MMA over K = 256 ----
            #pragma unroll
            for (int kk = 0; kk < 16; ++kk) {
                uint32_t a[2][4], b[4][4];
                uint32_t aoff = (uint32_t)(((2 * kk + aSel) ^ aR7) << 4);
                ldsm_x4(a[0][0], a[0][1], a[0][2], a[0][3], aB[0] + aoff);
                ldsm_x4(a[1][0], a[1][1], a[1][2], a[1][3], aB[1] + aoff);
                uint32_t boff = (uint32_t)(((2 * kk + bSel) ^ bR7) << 4) + bofs;
                #pragma unroll
                for (int p = 0; p < 4; ++p)
                    ldsm_x4(b[p][0], b[p][1], b[p][2], b[p][3], bB[p] + boff);
                #pragma unroll
                for (int mf = 0; mf < 2; ++mf)
                    #pragma unroll
                    for (int nf = 0; nf < 8; ++nf)
                        mma16816(acc[mf][nf], a[mf],
                                 b[nf >> 1][(nf & 1) * 2],
                                 b[nf >> 1][(nf & 1) * 2 + 1]);
            }

            // ---- epilogue (register-only + direct RED) ----
            const int bj = j0 + t;
            if (bj == bi)
                epilogue<true >(acc, rsum, 0, lane, dd);
            else
                epilogue<false>(acc, rsum, bj * 128 + wn * 64, lane, dd);
        }
    }

    if (cur_bi >= 0) flush_rsum(rsum, cur_bi, wm, lane);
}

// ============================ K3: loss (single kernel) ============================
__global__ void loss_kernel(float* __restrict__ out) {
    int r = blockIdx.x * 256 + threadIdx.x;
    double v = (double)logf(g_S[r]) + 10.0 - 10.0 * (double)g_pos[r];
    #pragma unroll
    for (int o = 16; o; o >>= 1) v += __shfl_xor_sync(0xffffffffu, v, o);
    __shared__ double sd[8];
    if ((threadIdx.x & 31) == 0) sd[threadIdx.x >> 5] = v;
    __syncthreads();
    if (threadIdx.x == 0) {
        double a = 0.0;
        #pragma unroll
        for (int i = 0; i < 8; ++i) a += sd[i];
        g_part[blockIdx.x] = a;
        __threadfence();
        int n = atomicAdd(&g_done, 1);
        if (n == 63) {
            __threadfence();
            double s = 0.0;
            for (int i = 0; i < 64; ++i)
                s += *((volatile double*)&g_part[i]);
            out[0] = (float)(s / (double)NROWS);
            g_done = 0;
        }
    }
}

// ---------------------------------------------------------------------------
extern "C" void kernel_launch(void* const* d_in, const int* in_sizes, int n_in,
                              void* d_out, int out_size) {
    (void)in_sizes; (void)n_in; (void)out_size;
    const float* z1 = (const float*)d_in[0];
    const float* z2 = (const float*)d_in[1];
    float* out = (float*)d_out;

    cudaFuncSetAttribute(gemm_sym_kernel,
                         cudaFuncAttributeMaxDynamicSharedMemorySize, SMEM_TOTAL);

    norm_pos_kernel<<<NHALF, 128>>>(z1, z2);
    gemm_sym_kernel<<<GRID_P, GT, SMEM_TOTAL>>>();
    loss_kernel<<<64, 256>>>(out);
}

// round 6
// speedup vs baseline: 1.4888x; 1.1285x over previous
#include <cuda_runtime.h>
#include <cuda_bf16.h>
#include <cstdint>
#include <math.h>

#define NROWS 16384
#define NHALF 8192
#define DDIM  256
#define NT    128
#define SEGW  8
#define NSEG  1088
#define GT    256
#define GRID_P 152

// ---- device scratch ----
__device__ __nv_bfloat16 g_zn[NROWS * DDIM];
__device__ float  g_pos[NROWS];
__device__ float  g_S[NROWS];
__device__ double g_part[64];
__device__ int    g_ticket;
__device__ int    g_done = 0;

// ---- gemm smem: A 64KB, then 4 pairs x 2 bufs x 16KB B slices ----
#define OFF_A    0
#define OFF_B    65536
#define OFF_BC   196608
#define SMEM_TOTAL 196624

#define C1F 14.42695040888963f   // 10*log2(e)

// ============================ helpers ============================
__device__ __forceinline__ uint32_t smem_u32(const void* p) {
    uint32_t a;
    asm("{ .reg .u64 t; cvta.to.shared.u64 t, %1; cvt.u32.u64 %0, t; }"
        : "=r"(a) : "l"(p));
    return a;
}
__device__ __forceinline__ void ldsm_x4(uint32_t& r0, uint32_t& r1,
                                        uint32_t& r2, uint32_t& r3,
                                        uint32_t addr) {
    asm volatile("ldmatrix.sync.aligned.m8n8.x4.shared.b16 {%0,%1,%2,%3}, [%4];"
                 : "=r"(r0), "=r"(r1), "=r"(r2), "=r"(r3) : "r"(addr));
}
__device__ __forceinline__ void mma16816(float* d, const uint32_t* a,
                                         uint32_t b0, uint32_t b1) {
    asm volatile(
        "mma.sync.aligned.m16n8k16.row.col.f32.bf16.bf16.f32 "
        "{%0,%1,%2,%3}, {%4,%5,%6,%7}, {%8,%9}, {%0,%1,%2,%3};"
        : "+f"(d[0]), "+f"(d[1]), "+f"(d[2]), "+f"(d[3])
        : "r"(a[0]), "r"(a[1]), "r"(a[2]), "r"(a[3]), "r"(b0), "r"(b1));
}
__device__ __forceinline__ float ex2f(float x) {
    float y; asm("ex2.approx.f32 %0, %1;" : "=f"(y) : "f"(x)); return y;
}
__device__ __forceinline__ void cp_commit() {
    asm volatile("cp.async.commit_group;" ::: "memory");
}
template <int N>
__device__ __forceinline__ void cp_wait() {
    asm volatile("cp.async.wait_group %0;" :: "n"(N) : "memory");
}
__device__ __forceinline__ void bar_pair(int id) {
    asm volatile("bar.sync %0, 64;" :: "r"(id) : "memory");
}
// full-CTA cooperative A tile load (128 rows x 512B, swizzled)
__device__ __forceinline__ void cp_tile_A(uint32_t sdst, int rowblk, int tid) {
    const char* gp = reinterpret_cast<const char*>(g_zn) + (size_t)rowblk * 65536;
    #pragma unroll
    for (int it = 0; it < 16; ++it) {
        int c = tid + it * GT;
        int r = c >> 5, cc = c & 31;
        uint32_t d = sdst + r * 512 + (((cc ^ (r & 7))) << 4);
        asm volatile("cp.async.cg.shared.global [%0], [%1], 16;"
                     :: "r"(d), "l"(gp + (size_t)c * 16) : "memory");
    }
}
// pair-private B slice: 32 rows x 512B, loaded by 64 threads (pairtid 0..63)
__device__ __forceinline__ void cp_slice_B(uint32_t sdst, int bj, int wn,
                                           int pairtid) {
    const char* gp = reinterpret_cast<const char*>(g_zn)
                     + ((size_t)bj * 128 + wn * 32) * 512;
    #pragma unroll
    for (int it = 0; it < 16; ++it) {
        int c = pairtid + it * 64;        // 0..1023 16B-chunks
        int r = c >> 5, cc = c & 31;
        uint32_t d = sdst + r * 512 + (((cc ^ (r & 7))) << 4);
        asm volatile("cp.async.cg.shared.global [%0], [%1], 16;"
                     :: "r"(d), "l"(gp + (size_t)c * 16) : "memory");
    }
}

// ============================ K1: normalize + positives ============================
__global__ void norm_pos_kernel(const float* __restrict__ z1,
                                const float* __restrict__ z2) {
    int r = blockIdx.x;
    int t = threadIdx.x;          // 0..127
    int half = t >> 6, tt = t & 63;
    const float* src = (half ? z2 : z1) + (size_t)r * DDIM;
    float4 v = reinterpret_cast<const float4*>(src)[tt];
    float ss = v.x * v.x + v.y * v.y + v.z * v.z + v.w * v.w;
    #pragma unroll
    for (int o = 16; o; o >>= 1) ss += __shfl_xor_sync(0xffffffffu, ss, o);
    __shared__ float ws[4];
    __shared__ float sn[2][256];
    if ((t & 31) == 0) ws[t >> 5] = ss;
    __syncthreads();
    float inv = 1.0f / fmaxf(sqrtf(ws[half * 2] + ws[half * 2 + 1]), 1e-6f);
    float4 n;
    n.x = v.x * inv; n.y = v.y * inv; n.z = v.z * inv; n.w = v.w * inv;
    __nv_bfloat162 h0 = __floats2bfloat162_rn(n.x, n.y);
    __nv_bfloat162 h1 = __floats2bfloat162_rn(n.z, n.w);
    uint2 packed;
    packed.x = *reinterpret_cast<uint32_t*>(&h0);
    packed.y = *reinterpret_cast<uint32_t*>(&h1);
    int row = half ? r + NHALF : r;
    reinterpret_cast<uint2*>(g_zn + (size_t)row * DDIM)[tt] = packed;
    reinterpret_cast<float4*>(sn[half])[tt] = n;
    __syncthreads();
    float p = sn[0][t * 2] * sn[1][t * 2] + sn[0][t * 2 + 1] * sn[1][t * 2 + 1];
    #pragma unroll
    for (int o = 16; o; o >>= 1) p += __shfl_xor_sync(0xffffffffu, p, o);
    if ((t & 31) == 0) ws[t >> 5] = p;
    __syncthreads();
    if (t == 0) {
        float d = fminf(fmaxf(ws[0] + ws[1] + ws[2] + ws[3], -1.0f + 1e-6f),
                        1.0f - 1e-6f);
        g_pos[r] = d;
        g_pos[r + NHALF] = d;
        g_S[r] = 0.f;
        g_S[r + NHALF] = 0.f;
        if (r == 0) g_ticket = 0;
    }
}

// ===================== K2: persistent symmetric GEMM + LSE =====================
// warp layout: wn = wid>>1 (0..3, 32-col slice), wm = wid&1 (0..1, 64-row half)
template <bool MASK>
__device__ __forceinline__ void epilogue(float (&acc)[4][4][4],
                                         float (&rsum)[4][2],
                                         int colbase,   // bj*128 + wn*32
                                         int lane, const uint32_t* dd) {
    float csum[4][2];
    #pragma unroll
    for (int nf = 0; nf < 4; ++nf) { csum[nf][0] = 0.f; csum[nf][1] = 0.f; }
    #pragma unroll
    for (int mf = 0; mf < 4; ++mf)
        #pragma unroll
        for (int nf = 0; nf < 4; ++nf)
            #pragma unroll
            for (int e = 0; e < 4; ++e) {
                float ev = ex2f(fmaf(acc[mf][nf][e], C1F, -C1F));
                if (MASK) {
                    uint32_t id = (uint32_t)(((mf * 4 + nf) << 2) + e);
                    if (id == dd[0] || id == dd[1] || id == dd[2] || id == dd[3])
                        ev = 0.f;
                }
                rsum[mf][e >> 1] += ev;
                if (!MASK) csum[nf][e & 1] += ev;
                acc[mf][nf][e] = 0.f;
            }
    if (!MASK) {
        const int q = lane & 3;
        #pragma unroll
        for (int nf = 0; nf < 4; ++nf)
            #pragma unroll
            for (int e1 = 0; e1 < 2; ++e1) {
                float v = csum[nf][e1];
                v += __shfl_xor_sync(0xffffffffu, v, 4);
                v += __shfl_xor_sync(0xffffffffu, v, 8);
                v += __shfl_xor_sync(0xffffffffu, v, 16);
                if (lane < 4)
                    atomicAdd(&g_S[colbase + nf * 8 + q * 2 + e1], v);
            }
    }
}

__device__ __forceinline__ void flush_rsum(float (&rsum)[4][2], int bi,
                                           int wm, int lane) {
    const int g = lane >> 2, q = lane & 3;
    #pragma unroll
    for (int mf = 0; mf < 4; ++mf)
        #pragma unroll
        for (int h = 0; h < 2; ++h) {
            float v = rsum[mf][h];
            v += __shfl_xor_sync(0xffffffffu, v, 1);
            v += __shfl_xor_sync(0xffffffffu, v, 2);
            if (q == 0)
                atomicAdd(&g_S[bi * 128 + wm * 64 + mf * 16 + h * 8 + g], v);
            rsum[mf][h] = 0.f;
        }
}

__global__ void __launch_bounds__(GT, 1) gemm_sym_kernel() {
    extern __shared__ char smem[];
    const int tid = threadIdx.x, lane = tid & 31, wid = tid >> 5;
    const int wn = wid >> 1, wm = wid & 1;
    const int pairtid = (wid & 1) * 32 + lane;
    const int g = lane >> 2, q = lane & 3;
    uint32_t sb = smem_u32(smem);
    int* sBC = reinterpret_cast<int*>(smem + OFF_BC);

    // fragment addressing
    const int aRow = lane & 15;
    const int aSel = lane >> 4;
    const int bRowOff = (lane & 7) + ((lane >> 4) << 3);
    const int bSel = (lane >> 3) & 1;
    const int aR7 = aRow & 7, bR7 = bRowOff & 7;
    uint32_t aB[4];
    #pragma unroll
    for (int mf = 0; mf < 4; ++mf)
        aB[mf] = sb + OFF_A + (wm * 64 + mf * 16 + aRow) * 512;
    // two B buffers for this pair
    uint32_t sliceB[2];
    sliceB[0] = sb + OFF_B + (wn * 2) * 16384;
    sliceB[1] = sliceB[0] + 16384;
    uint32_t bB[2][2];
    #pragma unroll
    for (int bf = 0; bf < 2; ++bf)
        #pragma unroll
        for (int p = 0; p < 2; ++p)
            bB[bf][p] = sliceB[bf] + (p * 16 + bRowOff) * 512;

    // diag element ids: row = wm*64+mf*16+e2*8+g, col = wn*32+nf*8+q*2+e1
    const bool qual = ((wn >> 1) == wm) && (q == (g >> 1));
    const int e1b = g & 1;
    uint32_t dd[4];
    {
        int base = (wn & 1) * 4;   // mf offset: wn even -> mf 0,1 ; odd -> 2,3
        #pragma unroll
        for (int k = 0; k < 4; ++k) {
            int mf = base ? (2 + (k >> 1)) : (k >> 1);
            int e2 = k & 1;
            int nf = mf * 2 + e2 - (base ? 4 : 0);
            dd[k] = qual ? (uint32_t)(((mf * 4 + nf) << 2) + e2 * 2 + e1b) : 255u;
        }
    }

    float acc[4][4][4];
    #pragma unroll
    for (int mf = 0; mf < 4; ++mf)
        #pragma unroll
        for (int nf = 0; nf < 4; ++nf)
            #pragma unroll
            for (int e = 0; e < 4; ++e) acc[mf][nf][e] = 0.f;
    float rsum[4][2];
    #pragma unroll
    for (int mf = 0; mf < 4; ++mf) { rsum[mf][0] = 0.f; rsum[mf][1] = 0.f; }

    const int barid = 1 + wn;
    int cur_bi = -1;

    for (;;) {
        if (tid == 0) sBC[0] = atomicAdd(&g_ticket, 1);
        __syncthreads();
        int c = sBC[0];
        if (c >= NSEG) break;

        int idx = c, bi = 0;
        for (;;) {
            int ns = (NT - bi + SEGW - 1) >> 3;
            if (idx < ns) break;
            idx -= ns; ++bi;
        }
        const int j0 = bi + idx * SEGW;
        const int len = min(SEGW, NT - j0);
        const bool reloadA = (bi != cur_bi);

        if (reloadA) {
            if (cur_bi >= 0) flush_rsum(rsum, cur_bi, wm, lane);
            cp_tile_A(sb + OFF_A, bi, tid);
            cp_commit();
            cur_bi = bi;
        }
        // prologue B: slice for tile0 (+ tile1)
        cp_slice_B(sliceB[0], j0, wn, pairtid);
        cp_commit();
        if (len > 1) {
            cp_slice_B(sliceB[1], j0 + 1, wn, pairtid);
            cp_commit();
        }
        if (reloadA) {
            // A must be complete and visible to all warps
            if (len > 1) cp_wait<2>(); else cp_wait<1>();
            __syncthreads();
        }

        for (int t = 0; t < len; ++t) {
            const int buf = t & 1;
            if (t < len - 1) cp_wait<1>(); else cp_wait<0>();
            bar_pair(barid);                 // pair's B(t) visible

            // ---- MMA over K = 256 ----
            #pragma unroll
            for (int kk = 0; kk < 16; ++kk) {
                uint32_t a[4][4], b[2][4];
                uint32_t aoff = (uint32_t)(((2 * kk + aSel) ^ aR7) << 4);
                #pragma unroll
                for (int mf = 0; mf < 4; ++mf)
                    ldsm_x4(a[mf][0], a[mf][1], a[mf][2], a[mf][3],
                            aB[mf] + aoff);
                uint32_t boff = (uint32_t)(((2 * kk + bSel) ^ bR7) << 4);
                #pragma unroll
                for (int p = 0; p < 2; ++p)
                    ldsm_x4(b[p][0], b[p][1], b[p][2], b[p][3],
                            bB[buf][p] + boff);
                #pragma unroll
                for (int mf = 0; mf < 4; ++mf)
                    #pragma unroll
                    for (int nf = 0; nf < 4; ++nf)
                        mma16816(acc[mf][nf], a[mf],
                                 b[nf >> 1][(nf & 1) * 2],
                                 b[nf >> 1][(nf & 1) * 2 + 1]);
            }
            bar_pair(barid);                 // both warps done reading buf
            if (t + 2 < len) {
                cp_slice_B(sliceB[buf], j0 + t + 2, wn, pairtid);
                cp_commit();
            }

            // ---- epilogue (register-only; overlaps other pairs' MMA) ----
            const int bj = j0 + t;
            if (bj == bi)
                epilogue<true >(acc, rsum, 0, lane, dd);
            else
                epilogue<false>(acc, rsum, bj * 128 + wn * 32, lane, dd);
        }
    }

    if (cur_bi >= 0) flush_rsum(rsum, cur_bi, wm, lane);
}

// ============================ K3: loss ============================
__global__ void loss_kernel(float* __restrict__ out) {
    int r = blockIdx.x * 256 + threadIdx.x;
    double v = (double)logf(g_S[r]) + 10.0 - 10.0 * (double)g_pos[r];
    #pragma unroll
    for (int o = 16; o; o >>= 1) v += __shfl_xor_sync(0xffffffffu, v, o);
    __shared__ double sd[8];
    if ((threadIdx.x & 31) == 0) sd[threadIdx.x >> 5] = v;
    __syncthreads();
    if (threadIdx.x == 0) {
        double a = 0.0;
        #pragma unroll
        for (int i = 0; i < 8; ++i) a += sd[i];
        g_part[blockIdx.x] = a;
        __threadfence();
        int n = atomicAdd(&g_done, 1);
        if (n == 63) {
            __threadfence();
            double s = 0.0;
            for (int i = 0; i < 64; ++i)
                s += *((volatile double*)&g_part[i]);
            out[0] = (float)(s / (double)NROWS);
            g_done = 0;
        }
    }
}

// ---------------------------------------------------------------------------
extern "C" void kernel_launch(void* const* d_in, const int* in_sizes, int n_in,
                              void* d_out, int out_size) {
    (void)in_sizes; (void)n_in; (void)out_size;
    const float* z1 = (const float*)d_in[0];
    const float* z2 = (const float*)d_in[1];
    float* out = (float*)d_out;

    cudaFuncSetAttribute(gemm_sym_kernel,
                         cudaFuncAttributeMaxDynamicSharedMemorySize, SMEM_TOTAL);

    norm_pos_kernel<<<NHALF, 128>>>(z1, z2);
    gemm_sym_kernel<<<GRID_P, GT, SMEM_TOTAL>>>();
    loss_kernel<<<64, 256>>>(out);
}